// round 15
// baseline (speedup 1.0000x reference)
#include <cuda_runtime.h>
#include <cuda_fp16.h>
#include <cstdint>

// q [B,N,D] fp32, k [B,M,D] fp32, out [B,N,M] fp32
#define BATCH 16
#define NROWS 2048
#define MCOLS 2048
#define DDIM  512
#define BM 128
#define BN 128
#define BK 64                 // fp16 k-cols per stage (128 B rows = SW128 atom)
#define NKT 8                 // stages per tile
#define NTM (MCOLS / BN)      // 16 tiles per row-block
#define NCTA 296              // persistent CTAs (2/SM on 148 SMs; fits 152 too)
#define TOTAL_TILES 4096

// ------------- static scratch (no allocation) -----------------------------
__device__ __align__(1024) __half g_Qh[(size_t)BATCH * NROWS * DDIM];   // 32MB
__device__ __align__(1024) __half g_Kh[(size_t)BATCH * MCOLS * DDIM];   // 32MB
__device__ __align__(1024) __half g_exp[(size_t)BATCH * NROWS * MCOLS]; // 128MB
__device__ float g_partial[(size_t)BATCH * NROWS * NTM];

// ------------- helpers -----------------------------------------------------
__device__ __forceinline__ uint32_t smem_u32(const void* p) {
    uint32_t a;
    asm("{ .reg .u64 t; cvta.to.shared.u64 t, %1; cvt.u32.u64 %0, t; }" : "=r"(a) : "l"(p));
    return a;
}
#define SW128(o) ((o) ^ (((o) >> 3) & 0x70))

__device__ __forceinline__ void cp16(uint32_t dst, const void* src) {
    asm volatile("cp.async.cg.shared.global [%0], [%1], 16;" :: "r"(dst), "l"(src) : "memory");
}
__device__ __forceinline__ void ldm_x4(uint32_t* r, uint32_t addr) {
    asm volatile("ldmatrix.sync.aligned.m8n8.x4.shared.b16 {%0,%1,%2,%3}, [%4];"
                 : "=r"(r[0]), "=r"(r[1]), "=r"(r[2]), "=r"(r[3]) : "r"(addr));
}
__device__ __forceinline__ void mma_fp16(float* c, const uint32_t* a, uint32_t b0, uint32_t b1) {
    asm volatile(
        "mma.sync.aligned.m16n8k16.row.col.f32.f16.f16.f32 "
        "{%0,%1,%2,%3}, {%4,%5,%6,%7}, {%8,%9}, {%0,%1,%2,%3};"
        : "+f"(c[0]), "+f"(c[1]), "+f"(c[2]), "+f"(c[3])
        : "r"(a[0]), "r"(a[1]), "r"(a[2]), "r"(a[3]), "r"(b0), "r"(b1));
}
__device__ __forceinline__ float ex2f(float x) {
    float y; asm("ex2.approx.ftz.f32 %0, %1;" : "=f"(y) : "f"(x)); return y;
}

// smem: 3 stages x (A 16KB + B 16KB) = 96KB, rowbuf @98304 (512B)
#define STAGE   32768
#define B_OFF   16384
#define RB_OFF  98304
#define SMEM_BYTES 98816

// ------------- fp32 -> fp16 conversion (Q pre-scaled by 512^-0.5 * log2e) --
__global__ __launch_bounds__(256)
void convert_kernel(const float4* __restrict__ q, const float4* __restrict__ k) {
    const float scale = 0.06376730196929233f;   // 512^-0.5 * log2(e)
    size_t i = (size_t)blockIdx.x * 256 + threadIdx.x;    // 4,194,304 total
    float4 v = q[i];
    __half2 a = __floats2half2_rn(v.x * scale, v.y * scale);
    __half2 b = __floats2half2_rn(v.z * scale, v.w * scale);
    ((__half2*)g_Qh)[i * 2]     = a;
    ((__half2*)g_Qh)[i * 2 + 1] = b;
    float4 w = k[i];
    a = __floats2half2_rn(w.x, w.y);
    b = __floats2half2_rn(w.z, w.w);
    ((__half2*)g_Kh)[i * 2]     = a;
    ((__half2*)g_Kh)[i * 2 + 1] = b;
}

// ------------- scores: persistent fp16 GEMM, cross-tile cp.async stream ----
// 128 threads = 4 warps in 2(wm) x 2(wn), 64x64 warp tiles, 2 CTAs/SM.
__global__ __launch_bounds__(128, 2)
void scores_kernel() {
    extern __shared__ __align__(128) char smem[];
    const uint32_t sb = smem_u32(smem);

    const int tid  = threadIdx.x;
    const int warp = tid >> 5;
    const int lane = tid & 31;
    const int wm = warp >> 1;          // 0..1  (rows 64*wm)
    const int wn = warp & 1;           // 0..1  (cols 64*wn)
    const int cta = blockIdx.x;        // 0..NCTA-1

    const int nt = (TOTAL_TILES - cta + NCTA - 1) / NCTA;   // 13 or 14 tiles
    const int T  = nt * NKT;           // total stages for this CTA

    float* rowbuf = (float*)(smem + RB_OFF);
    rowbuf[tid] = 0.f;                 // 128 threads == BM rows

    // load stage g of this CTA's continuous stage stream (tile decode = shifts)
    auto load_stage = [&](int g) {
        const int i  = g >> 3;
        const int kt = g & 7;
        const int tile = cta + i * NCTA;
        const int bi = tile >> 8, tn = (tile >> 4) & 15, tm = tile & 15;
        const __half* qt = g_Qh + ((size_t)bi * NROWS + (size_t)tn * BM) * DDIM;
        const __half* kp = g_Kh + ((size_t)bi * MCOLS + (size_t)tm * BN) * DDIM;
        const int buf = g % 3;
        #pragma unroll
        for (int it = 0; it < 16; it++) {
            int gg = tid + it * 128;
            int isB = gg >> 10;
            int c = gg & 1023;
            int row = c >> 3;
            int j = c & 7;                 // 16B chunk within 128B row
            uint32_t dst = sb + buf * STAGE + isB * B_OFF + SW128(row * 128 + j * 16);
            const __half* src = (isB ? kp : qt) + (size_t)row * DDIM + kt * BK + j * 8;
            cp16(dst, src);
        }
        asm volatile("cp.async.commit_group;" ::: "memory");
    };

    // prologue: two stages in flight (T >= 104 always)
    load_stage(0);
    load_stage(1);

    // ldmatrix lane-address components (validated rounds 4/6-14)
    const int arow = (lane & 15);                        // + wm*64 + fm*16
    const int acolb = (lane >> 4) * 16;                  // k8-half select (bytes)
    const int brow = (lane & 7) + ((lane >> 4) << 3);    // + wn*64 + h*16
    const int bcolb = ((lane >> 3) & 1) * 16;

    for (int i = 0; i < nt; i++) {
        float acc[4][8][4];
        #pragma unroll
        for (int x = 0; x < 4; x++)
            #pragma unroll
            for (int y = 0; y < 8; y++)
                #pragma unroll
                for (int c = 0; c < 4; c++) acc[x][y][c] = 0.f;

        for (int kt = 0; kt < NKT; kt++) {
            const int g = i * NKT + kt;
            if (g + 1 < T) asm volatile("cp.async.wait_group 1;" ::: "memory");
            else           asm volatile("cp.async.wait_group 0;" ::: "memory");
            __syncthreads();               // single barrier per stage

            if (g + 2 < T) load_stage(g + 2);   // writes buf (g-1)%3 — barrier-protected

            const int sbuf = g % 3;
            const uint32_t abase = sb + sbuf * STAGE;
            const uint32_t bbase = abase + B_OFF;

            // software-pipelined kk loop: double-buffered fragments
            uint32_t af[2][4][4], bf[2][4][4];
            #pragma unroll
            for (int fm = 0; fm < 4; fm++) {
                int r = wm * 64 + fm * 16 + arow;
                ldm_x4(af[0][fm], abase + SW128(r * 128 + acolb));
            }
            #pragma unroll
            for (int h = 0; h < 4; h++) {
                int r = wn * 64 + h * 16 + brow;
                ldm_x4(bf[0][h], bbase + SW128(r * 128 + bcolb));
            }
            #pragma unroll
            for (int kk = 0; kk < 4; kk++) {
                const int cur = kk & 1, nxt = cur ^ 1;
                if (kk < 3) {
                    #pragma unroll
                    for (int fm = 0; fm < 4; fm++) {
                        int r = wm * 64 + fm * 16 + arow;
                        ldm_x4(af[nxt][fm], abase + SW128(r * 128 + (kk + 1) * 32 + acolb));
                    }
                    #pragma unroll
                    for (int h = 0; h < 4; h++) {
                        int r = wn * 64 + h * 16 + brow;
                        ldm_x4(bf[nxt][h], bbase + SW128(r * 128 + (kk + 1) * 32 + bcolb));
                    }
                }
                #pragma unroll
                for (int fm = 0; fm < 4; fm++)
                    #pragma unroll
                    for (int h = 0; h < 4; h++)
                        #pragma unroll
                        for (int sub = 0; sub < 2; sub++)
                            mma_fp16(acc[fm][h * 2 + sub], af[cur][fm],
                                     bf[cur][h][sub * 2], bf[cur][h][sub * 2 + 1]);
            }
        }

        // ---- epilogue (next tile's cp.async stages already in flight) ----
        const int tile = cta + i * NCTA;
        const int bi = tile >> 8, tn = (tile >> 4) & 15, tm = tile & 15;
        __half* eb = g_exp + ((size_t)bi * NROWS + (size_t)tn * BM) * MCOLS + (size_t)tm * BN;

        #pragma unroll
        for (int fm = 0; fm < 4; fm++) {
            const int r0 = wm * 64 + fm * 16 + (lane >> 2);
            const int r1 = r0 + 8;
            float s0 = 0.f, s1 = 0.f;
            #pragma unroll
            for (int fn = 0; fn < 8; fn++) {
                const int gcol = wn * 64 + fn * 8 + (lane & 3) * 2;
                float p00 = ex2f(acc[fm][fn][0]);    // Q pre-scaled by log2(e)/sqrt(d)
                float p01 = ex2f(acc[fm][fn][1]);
                float p10 = ex2f(acc[fm][fn][2]);
                float p11 = ex2f(acc[fm][fn][3]);
                *reinterpret_cast<__half2*>(eb + (size_t)r0 * MCOLS + gcol) = __floats2half2_rn(p00, p01);
                *reinterpret_cast<__half2*>(eb + (size_t)r1 * MCOLS + gcol) = __floats2half2_rn(p10, p11);
                s0 += p00 + p01;
                s1 += p10 + p11;
            }
            s0 += __shfl_xor_sync(0xffffffffu, s0, 1);
            s0 += __shfl_xor_sync(0xffffffffu, s0, 2);
            s1 += __shfl_xor_sync(0xffffffffu, s1, 1);
            s1 += __shfl_xor_sync(0xffffffffu, s1, 2);
            if ((lane & 3) == 0) {
                atomicAdd(&rowbuf[r0], s0);
                atomicAdd(&rowbuf[r1], s1);
            }
        }
        __syncthreads();
        {
            size_t row = (size_t)bi * NROWS + (size_t)tn * BM + tid;
            g_partial[row * NTM + tm] = rowbuf[tid];
            rowbuf[tid] = 0.f;   // reset for next tile; ordered by next stage barrier
        }
    }
}

// ------------- normalize: read fp16 exp, write fp32 out (forward, default) -
__global__ __launch_bounds__(256)
void norm_kernel(float* __restrict__ out) {
    const size_t r0 = (size_t)blockIdx.x * 2;
    float sa = 0.f, sb = 0.f;
    #pragma unroll
    for (int i = 0; i < NTM; i++) {
        sa += g_partial[r0 * NTM + i];
        sb += g_partial[(r0 + 1) * NTM + i];
    }
    const float ra = 1.0f / sa, rb = 1.0f / sb;

    const __half2* ea  = (const __half2*)(g_exp + r0 * MCOLS);
    const __half2* ebp = (const __half2*)(g_exp + (r0 + 1) * MCOLS);
    float4* oa = (float4*)(out + r0 * MCOLS);
    float4* ob = (float4*)(out + (r0 + 1) * MCOLS);
    const int t = threadIdx.x;

    #pragma unroll
    for (int j = 0; j < 2; j++) {
        int i = t + j * 256;                 // 0..511 float4 per row
        float2 f0 = __half22float2(ea[2 * i]);
        float2 f1 = __half22float2(ea[2 * i + 1]);
        float4 v; v.x = f0.x * ra; v.y = f0.y * ra; v.z = f1.x * ra; v.w = f1.y * ra;
        oa[i] = v;
        f0 = __half22float2(ebp[2 * i]);
        f1 = __half22float2(ebp[2 * i + 1]);
        v.x = f0.x * rb; v.y = f0.y * rb; v.z = f1.x * rb; v.w = f1.y * rb;
        ob[i] = v;
    }
}

// ------------- launch --------------------------------------------------------
extern "C" void kernel_launch(void* const* d_in, const int* in_sizes, int n_in,
                              void* d_out, int out_size) {
    const float4* q = (const float4*)d_in[0];
    const float4* k = (const float4*)d_in[1];
    float* out = (float*)d_out;

    cudaFuncSetAttribute(scores_kernel,
                         cudaFuncAttributeMaxDynamicSharedMemorySize, SMEM_BYTES);

    convert_kernel<<<16384, 256>>>(q, k);
    scores_kernel<<<NCTA, 128, SMEM_BYTES>>>();
    norm_kernel<<<BATCH * NROWS / 2, 256>>>(out);
}

// round 16
// speedup vs baseline: 1.0451x; 1.0451x over previous
#include <cuda_runtime.h>
#include <cuda_fp16.h>
#include <cstdint>

// q [B,N,D] fp32, k [B,M,D] fp32, out [B,N,M] fp32
#define BATCH 16
#define NROWS 2048
#define MCOLS 2048
#define DDIM  512
#define BM 128
#define BN 128
#define BK 64                 // fp16 k-cols per stage (128 B rows = SW128 atom)
#define NKT (DDIM / BK)       // 8
#define NTM (MCOLS / BN)      // 16 tiles per row-block

// ------------- static scratch (no allocation) -----------------------------
__device__ __align__(1024) __half g_Qh[(size_t)BATCH * NROWS * DDIM];   // 32MB
__device__ __align__(1024) __half g_Kh[(size_t)BATCH * MCOLS * DDIM];   // 32MB
__device__ __align__(1024) __half g_exp[(size_t)BATCH * NROWS * MCOLS]; // 128MB
__device__ float g_partial[(size_t)BATCH * NROWS * NTM];

// ------------- helpers -----------------------------------------------------
__device__ __forceinline__ uint32_t smem_u32(const void* p) {
    uint32_t a;
    asm("{ .reg .u64 t; cvta.to.shared.u64 t, %1; cvt.u32.u64 %0, t; }" : "=r"(a) : "l"(p));
    return a;
}
#define SW128(o) ((o) ^ (((o) >> 3) & 0x70))

__device__ __forceinline__ void cp16(uint32_t dst, const void* src) {
    asm volatile("cp.async.cg.shared.global [%0], [%1], 16;" :: "r"(dst), "l"(src) : "memory");
}
__device__ __forceinline__ void ldm_x4(uint32_t* r, uint32_t addr) {
    asm volatile("ldmatrix.sync.aligned.m8n8.x4.shared.b16 {%0,%1,%2,%3}, [%4];"
                 : "=r"(r[0]), "=r"(r[1]), "=r"(r[2]), "=r"(r[3]) : "r"(addr));
}
__device__ __forceinline__ void mma_fp16(float* c, const uint32_t* a, uint32_t b0, uint32_t b1) {
    asm volatile(
        "mma.sync.aligned.m16n8k16.row.col.f32.f16.f16.f32 "
        "{%0,%1,%2,%3}, {%4,%5,%6,%7}, {%8,%9}, {%0,%1,%2,%3};"
        : "+f"(c[0]), "+f"(c[1]), "+f"(c[2]), "+f"(c[3])
        : "r"(a[0]), "r"(a[1]), "r"(a[2]), "r"(a[3]), "r"(b0), "r"(b1));
}
__device__ __forceinline__ float ex2f(float x) {
    float y; asm("ex2.approx.ftz.f32 %0, %1;" : "=f"(y) : "f"(x)); return y;
}

// smem: 3 stages x (A 16KB + B 16KB) = 96KB, rowbuf @98304 (512B)
#define STAGE   32768
#define B_OFF   16384
#define RB_OFF  98304
#define SMEM_BYTES 98816

// ------------- fp32 -> fp16 conversion (Q pre-scaled by 512^-0.5 * log2e) --
__global__ __launch_bounds__(256)
void convert_kernel(const float4* __restrict__ q, const float4* __restrict__ k) {
    const float scale = 0.06376730196929233f;   // 512^-0.5 * log2(e)
    size_t i = (size_t)blockIdx.x * 256 + threadIdx.x;    // 4,194,304 total
    float4 v = q[i];
    __half2 a = __floats2half2_rn(v.x * scale, v.y * scale);
    __half2 b = __floats2half2_rn(v.z * scale, v.w * scale);
    ((__half2*)g_Qh)[i * 2]     = a;
    ((__half2*)g_Qh)[i * 2 + 1] = b;
    float4 w = k[i];
    a = __floats2half2_rn(w.x, w.y);
    b = __floats2half2_rn(w.z, w.w);
    ((__half2*)g_Kh)[i * 2]     = a;
    ((__half2*)g_Kh)[i * 2 + 1] = b;
}

// ------------- scores: fp16 GEMM, 4 warps x (64x64), 2 CTAs/SM -------------
// 128 threads = 4 warps in 2(wm) x 2(wn). kk loop software-pipelined.
// Next-stage cp.async issuance split into halves interleaved with mma bursts.
__global__ __launch_bounds__(128, 2)
void scores_kernel() {
    extern __shared__ __align__(128) char smem[];
    const uint32_t sb = smem_u32(smem);

    const int tid  = threadIdx.x;
    const int warp = tid >> 5;
    const int lane = tid & 31;
    const int wm = warp >> 1;          // 0..1  (rows 64*wm)
    const int wn = warp & 1;           // 0..1  (cols 64*wn)
    const int bi = blockIdx.z, tn = blockIdx.y, tm = blockIdx.x;

    const __half* qtile = g_Qh + ((size_t)bi * NROWS + (size_t)tn * BM) * DDIM;
    const __half* ktile = g_Kh + ((size_t)bi * MCOLS + (size_t)tm * BN) * DDIM;

    float* rowbuf = (float*)(smem + RB_OFF);
    rowbuf[tid] = 0.f;                 // init before any barrier; 128 thr == BM

    float acc[4][8][4];
    #pragma unroll
    for (int i = 0; i < 4; i++)
        #pragma unroll
        for (int j = 0; j < 8; j++)
            #pragma unroll
            for (int c = 0; c < 4; c++) acc[i][j][c] = 0.f;

    // issue half h (8 of 16) of a stage's 16B-chunk cp.asyncs
    auto load_half = [&](int buf, int kt, int h) {
        #pragma unroll
        for (int it = h * 8; it < h * 8 + 8; it++) {
            int g = tid + it * 128;
            int isB = g >> 10;
            int c = g & 1023;
            int row = c >> 3;
            int j = c & 7;                 // 16B chunk within 128B row
            uint32_t dst = sb + buf * STAGE + isB * B_OFF + SW128(row * 128 + j * 16);
            const __half* src = (isB ? ktile : qtile) +
                (size_t)row * DDIM + kt * BK + j * 8;
            cp16(dst, src);
        }
    };
    auto load_stage = [&](int buf, int kt) {
        load_half(buf, kt, 0);
        load_half(buf, kt, 1);
        asm volatile("cp.async.commit_group;" ::: "memory");
    };

    // prologue: two stages in flight
    load_stage(0, 0);
    load_stage(1, 1);

    // ldmatrix lane-address components (validated rounds 4/6-14)
    const int arow = (lane & 15);                        // + wm*64 + fm*16
    const int acolb = (lane >> 4) * 16;                  // k8-half select (bytes)
    const int brow = (lane & 7) + ((lane >> 4) << 3);    // + wn*64 + h*16
    const int bcolb = ((lane >> 3) & 1) * 16;

    int s = 0;                         // stage index = kt % 3
    for (int kt = 0; kt < NKT; kt++) {
        if (kt + 1 < NKT) asm volatile("cp.async.wait_group 1;" ::: "memory");
        else              asm volatile("cp.async.wait_group 0;" ::: "memory");
        __syncthreads();               // single barrier per iteration

        const bool more = (kt + 2 < NKT);
        int s2 = s + 2; if (s2 >= 3) s2 -= 3;

        const uint32_t abase = sb + s * STAGE;
        const uint32_t bbase = abase + B_OFF;

        // -------- fragments for kk=0 FIRST: mma starts right after barrier --
        uint32_t af[2][4][4], bf[2][4][4];
        #pragma unroll
        for (int fm = 0; fm < 4; fm++) {
            int r = wm * 64 + fm * 16 + arow;
            ldm_x4(af[0][fm], abase + SW128(r * 128 + acolb));
        }
        #pragma unroll
        for (int h = 0; h < 4; h++) {
            int r = wn * 64 + h * 16 + brow;
            ldm_x4(bf[0][h], bbase + SW128(r * 128 + bcolb));
        }
        // first half of next-stage loads rides under the kk0 fragment latency
        if (more) load_half(s2, kt + 2, 0);

        #pragma unroll
        for (int kk = 0; kk < 4; kk++) {
            const int cur = kk & 1, nxt = cur ^ 1;
            if (kk < 3) {
                #pragma unroll
                for (int fm = 0; fm < 4; fm++) {
                    int r = wm * 64 + fm * 16 + arow;
                    ldm_x4(af[nxt][fm], abase + SW128(r * 128 + (kk + 1) * 32 + acolb));
                }
                #pragma unroll
                for (int h = 0; h < 4; h++) {
                    int r = wn * 64 + h * 16 + brow;
                    ldm_x4(bf[nxt][h], bbase + SW128(r * 128 + (kk + 1) * 32 + bcolb));
                }
            }
            #pragma unroll
            for (int fm = 0; fm < 4; fm++)
                #pragma unroll
                for (int h = 0; h < 4; h++)
                    #pragma unroll
                    for (int sub = 0; sub < 2; sub++)
                        mma_fp16(acc[fm][h * 2 + sub], af[cur][fm],
                                 bf[cur][h][sub * 2], bf[cur][h][sub * 2 + 1]);
            // second half + commit after the kk0 mma burst
            if (kk == 0 && more) {
                load_half(s2, kt + 2, 1);
                asm volatile("cp.async.commit_group;" ::: "memory");
            }
        }
        if (++s >= 3) s -= 3;
    }

    // ------- epilogue: ex2 -> fp16 scratch + row-sum partials -------
    __half* eb = g_exp + ((size_t)bi * NROWS + (size_t)tn * BM) * MCOLS + (size_t)tm * BN;

    #pragma unroll
    for (int fm = 0; fm < 4; fm++) {
        const int r0 = wm * 64 + fm * 16 + (lane >> 2);
        const int r1 = r0 + 8;
        float s0 = 0.f, s1 = 0.f;
        #pragma unroll
        for (int fn = 0; fn < 8; fn++) {
            const int gcol = wn * 64 + fn * 8 + (lane & 3) * 2;
            float p00 = ex2f(acc[fm][fn][0]);   // Q pre-scaled by log2(e)/sqrt(d)
            float p01 = ex2f(acc[fm][fn][1]);
            float p10 = ex2f(acc[fm][fn][2]);
            float p11 = ex2f(acc[fm][fn][3]);
            *reinterpret_cast<__half2*>(eb + (size_t)r0 * MCOLS + gcol) = __floats2half2_rn(p00, p01);
            *reinterpret_cast<__half2*>(eb + (size_t)r1 * MCOLS + gcol) = __floats2half2_rn(p10, p11);
            s0 += p00 + p01;
            s1 += p10 + p11;
        }
        s0 += __shfl_xor_sync(0xffffffffu, s0, 1);
        s0 += __shfl_xor_sync(0xffffffffu, s0, 2);
        s1 += __shfl_xor_sync(0xffffffffu, s1, 1);
        s1 += __shfl_xor_sync(0xffffffffu, s1, 2);
        if ((lane & 3) == 0) {
            atomicAdd(&rowbuf[r0], s0);
            atomicAdd(&rowbuf[r1], s1);
        }
    }
    __syncthreads();

    {
        size_t row = (size_t)bi * NROWS + (size_t)tn * BM + tid;
        g_partial[row * NTM + tm] = rowbuf[tid];
    }
}

// ------------- normalize: read fp16 exp, write fp32 out (forward order) ----
__global__ __launch_bounds__(256)
void norm_kernel(float* __restrict__ out) {
    const size_t r0 = (size_t)blockIdx.x * 2;
    float sa = 0.f, sb = 0.f;
    #pragma unroll
    for (int i = 0; i < NTM; i++) {
        sa += g_partial[r0 * NTM + i];
        sb += g_partial[(r0 + 1) * NTM + i];
    }
    const float ra = 1.0f / sa, rb = 1.0f / sb;

    const __half2* ea  = (const __half2*)(g_exp + r0 * MCOLS);
    const __half2* ebp = (const __half2*)(g_exp + (r0 + 1) * MCOLS);
    float4* oa = (float4*)(out + r0 * MCOLS);
    float4* ob = (float4*)(out + (r0 + 1) * MCOLS);
    const int t = threadIdx.x;

    #pragma unroll
    for (int j = 0; j < 2; j++) {
        int i = t + j * 256;                 // 0..511 float4 per row
        float2 f0 = __half22float2(ea[2 * i]);
        float2 f1 = __half22float2(ea[2 * i + 1]);
        float4 v; v.x = f0.x * ra; v.y = f0.y * ra; v.z = f1.x * ra; v.w = f1.y * ra;
        oa[i] = v;
        f0 = __half22float2(ebp[2 * i]);
        f1 = __half22float2(ebp[2 * i + 1]);
        v.x = f0.x * rb; v.y = f0.y * rb; v.z = f1.x * rb; v.w = f1.y * rb;
        ob[i] = v;
    }
}

// ------------- launch --------------------------------------------------------
extern "C" void kernel_launch(void* const* d_in, const int* in_sizes, int n_in,
                              void* d_out, int out_size) {
    const float4* q = (const float4*)d_in[0];
    const float4* k = (const float4*)d_in[1];
    float* out = (float*)d_out;

    cudaFuncSetAttribute(scores_kernel,
                         cudaFuncAttributeMaxDynamicSharedMemorySize, SMEM_BYTES);

    convert_kernel<<<16384, 256>>>(q, k);
    dim3 grid(NTM, NROWS / BM, BATCH);   // 16 x 16 x 16
    scores_kernel<<<grid, 128, SMEM_BYTES>>>();
    norm_kernel<<<BATCH * NROWS / 2, 256>>>(out);
}

// round 17
// speedup vs baseline: 1.0899x; 1.0429x over previous
#include <cuda_runtime.h>
#include <cuda_fp16.h>
#include <cstdint>

// q [B,N,D] fp32, k [B,M,D] fp32, out [B,N,M] fp32
#define BATCH 16
#define NROWS 2048
#define MCOLS 2048
#define DDIM  512
#define BM 128
#define BN 128
#define BK 64                 // fp16 k-cols per stage (128 B rows = SW128 atom)
#define NKT (DDIM / BK)       // 8
#define NTM (MCOLS / BN)      // 16 tiles per row-block

// ------------- static scratch (no allocation) -----------------------------
__device__ __align__(1024) __half g_Qh[(size_t)BATCH * NROWS * DDIM];   // 32MB
__device__ __align__(1024) __half g_Kh[(size_t)BATCH * MCOLS * DDIM];   // 32MB
__device__ __align__(1024) __half g_exp[(size_t)BATCH * NROWS * MCOLS]; // 128MB
__device__ float g_partial[(size_t)BATCH * NROWS * NTM];

// ------------- helpers -----------------------------------------------------
__device__ __forceinline__ uint32_t smem_u32(const void* p) {
    uint32_t a;
    asm("{ .reg .u64 t; cvta.to.shared.u64 t, %1; cvt.u32.u64 %0, t; }" : "=r"(a) : "l"(p));
    return a;
}
#define SW128(o) ((o) ^ (((o) >> 3) & 0x70))

__device__ __forceinline__ void cp16(uint32_t dst, const void* src) {
    asm volatile("cp.async.cg.shared.global [%0], [%1], 16;" :: "r"(dst), "l"(src) : "memory");
}
__device__ __forceinline__ void ldm_x4(uint32_t* r, uint32_t addr) {
    asm volatile("ldmatrix.sync.aligned.m8n8.x4.shared.b16 {%0,%1,%2,%3}, [%4];"
                 : "=r"(r[0]), "=r"(r[1]), "=r"(r[2]), "=r"(r[3]) : "r"(addr));
}
__device__ __forceinline__ void mma_fp16(float* c, const uint32_t* a, uint32_t b0, uint32_t b1) {
    asm volatile(
        "mma.sync.aligned.m16n8k16.row.col.f32.f16.f16.f32 "
        "{%0,%1,%2,%3}, {%4,%5,%6,%7}, {%8,%9}, {%0,%1,%2,%3};"
        : "+f"(c[0]), "+f"(c[1]), "+f"(c[2]), "+f"(c[3])
        : "r"(a[0]), "r"(a[1]), "r"(a[2]), "r"(a[3]), "r"(b0), "r"(b1));
}
__device__ __forceinline__ float ex2f(float x) {
    float y; asm("ex2.approx.ftz.f32 %0, %1;" : "=f"(y) : "f"(x)); return y;
}

// smem: 3 stages x (A 16KB + B 16KB) = 96KB, rowbuf @98304 (512B)
// Epilogue reuses [0 .. 34816) as a 128 x 272B-pitch fp16 staging tile.
#define STAGE   32768
#define B_OFF   16384
#define RB_OFF  98304
#define SMEM_BYTES 98816
#define EP_PITCH 272          // 16B-aligned rows; bank shift 4/row -> conflict-free STS

// ------------- fp32 -> fp16 conversion (Q pre-scaled by 512^-0.5 * log2e) --
__global__ __launch_bounds__(256)
void convert_kernel(const float4* __restrict__ q, const float4* __restrict__ k) {
    const float scale = 0.06376730196929233f;   // 512^-0.5 * log2(e)
    size_t i = (size_t)blockIdx.x * 256 + threadIdx.x;    // 4,194,304 total
    float4 v = q[i];
    __half2 a = __floats2half2_rn(v.x * scale, v.y * scale);
    __half2 b = __floats2half2_rn(v.z * scale, v.w * scale);
    ((__half2*)g_Qh)[i * 2]     = a;
    ((__half2*)g_Qh)[i * 2 + 1] = b;
    float4 w = k[i];
    a = __floats2half2_rn(w.x, w.y);
    b = __floats2half2_rn(w.z, w.w);
    ((__half2*)g_Kh)[i * 2]     = a;
    ((__half2*)g_Kh)[i * 2 + 1] = b;
}

// ------------- scores: fp16 GEMM, 4 warps x (64x64), 2 CTAs/SM -------------
// 128 threads = 4 warps in 2(wm) x 2(wn). kk loop software-pipelined.
// Next-stage cp.async issuance split into halves interleaved with mma bursts.
// Epilogue staged through smem for coalesced 16B global stores.
__global__ __launch_bounds__(128, 2)
void scores_kernel() {
    extern __shared__ __align__(128) char smem[];
    const uint32_t sb = smem_u32(smem);

    const int tid  = threadIdx.x;
    const int warp = tid >> 5;
    const int lane = tid & 31;
    const int wm = warp >> 1;          // 0..1  (rows 64*wm)
    const int wn = warp & 1;           // 0..1  (cols 64*wn)
    const int bi = blockIdx.z, tn = blockIdx.y, tm = blockIdx.x;

    const __half* qtile = g_Qh + ((size_t)bi * NROWS + (size_t)tn * BM) * DDIM;
    const __half* ktile = g_Kh + ((size_t)bi * MCOLS + (size_t)tm * BN) * DDIM;

    float* rowbuf = (float*)(smem + RB_OFF);
    rowbuf[tid] = 0.f;                 // init before any barrier; 128 thr == BM

    float acc[4][8][4];
    #pragma unroll
    for (int i = 0; i < 4; i++)
        #pragma unroll
        for (int j = 0; j < 8; j++)
            #pragma unroll
            for (int c = 0; c < 4; c++) acc[i][j][c] = 0.f;

    // issue half h (8 of 16) of a stage's 16B-chunk cp.asyncs
    auto load_half = [&](int buf, int kt, int h) {
        #pragma unroll
        for (int it = h * 8; it < h * 8 + 8; it++) {
            int g = tid + it * 128;
            int isB = g >> 10;
            int c = g & 1023;
            int row = c >> 3;
            int j = c & 7;                 // 16B chunk within 128B row
            uint32_t dst = sb + buf * STAGE + isB * B_OFF + SW128(row * 128 + j * 16);
            const __half* src = (isB ? ktile : qtile) +
                (size_t)row * DDIM + kt * BK + j * 8;
            cp16(dst, src);
        }
    };
    auto load_stage = [&](int buf, int kt) {
        load_half(buf, kt, 0);
        load_half(buf, kt, 1);
        asm volatile("cp.async.commit_group;" ::: "memory");
    };

    // prologue: two stages in flight
    load_stage(0, 0);
    load_stage(1, 1);

    // ldmatrix lane-address components (validated rounds 4/6-16)
    const int arow = (lane & 15);                        // + wm*64 + fm*16
    const int acolb = (lane >> 4) * 16;                  // k8-half select (bytes)
    const int brow = (lane & 7) + ((lane >> 4) << 3);    // + wn*64 + h*16
    const int bcolb = ((lane >> 3) & 1) * 16;

    int s = 0;                         // stage index = kt % 3
    for (int kt = 0; kt < NKT; kt++) {
        if (kt + 1 < NKT) asm volatile("cp.async.wait_group 1;" ::: "memory");
        else              asm volatile("cp.async.wait_group 0;" ::: "memory");
        __syncthreads();               // single barrier per iteration

        const bool more = (kt + 2 < NKT);
        int s2 = s + 2; if (s2 >= 3) s2 -= 3;

        const uint32_t abase = sb + s * STAGE;
        const uint32_t bbase = abase + B_OFF;

        // -------- fragments for kk=0 FIRST: mma starts right after barrier --
        uint32_t af[2][4][4], bf[2][4][4];
        #pragma unroll
        for (int fm = 0; fm < 4; fm++) {
            int r = wm * 64 + fm * 16 + arow;
            ldm_x4(af[0][fm], abase + SW128(r * 128 + acolb));
        }
        #pragma unroll
        for (int h = 0; h < 4; h++) {
            int r = wn * 64 + h * 16 + brow;
            ldm_x4(bf[0][h], bbase + SW128(r * 128 + bcolb));
        }
        // first half of next-stage loads rides under the kk0 fragment latency
        if (more) load_half(s2, kt + 2, 0);

        #pragma unroll
        for (int kk = 0; kk < 4; kk++) {
            const int cur = kk & 1, nxt = cur ^ 1;
            if (kk < 3) {
                #pragma unroll
                for (int fm = 0; fm < 4; fm++) {
                    int r = wm * 64 + fm * 16 + arow;
                    ldm_x4(af[nxt][fm], abase + SW128(r * 128 + (kk + 1) * 32 + acolb));
                }
                #pragma unroll
                for (int h = 0; h < 4; h++) {
                    int r = wn * 64 + h * 16 + brow;
                    ldm_x4(bf[nxt][h], bbase + SW128(r * 128 + (kk + 1) * 32 + bcolb));
                }
            }
            #pragma unroll
            for (int fm = 0; fm < 4; fm++)
                #pragma unroll
                for (int h = 0; h < 4; h++)
                    #pragma unroll
                    for (int sub = 0; sub < 2; sub++)
                        mma_fp16(acc[fm][h * 2 + sub], af[cur][fm],
                                 bf[cur][h][sub * 2], bf[cur][h][sub * 2 + 1]);
            // second half + commit after the kk0 mma burst
            if (kk == 0 && more) {
                load_half(s2, kt + 2, 1);
                asm volatile("cp.async.commit_group;" ::: "memory");
            }
        }
        if (++s >= 3) s -= 3;
    }
    __syncthreads();                   // mainloop done; stage smem now free

    // ------- epilogue: ex2 -> smem staging (fp16) + row-sum partials -------
    #pragma unroll
    for (int fm = 0; fm < 4; fm++) {
        const int r0 = wm * 64 + fm * 16 + (lane >> 2);
        const int r1 = r0 + 8;
        float s0 = 0.f, s1 = 0.f;
        #pragma unroll
        for (int fn = 0; fn < 8; fn++) {
            const int gcol = wn * 64 + fn * 8 + (lane & 3) * 2;
            float p00 = ex2f(acc[fm][fn][0]);   // Q pre-scaled by log2(e)/sqrt(d)
            float p01 = ex2f(acc[fm][fn][1]);
            float p10 = ex2f(acc[fm][fn][2]);
            float p11 = ex2f(acc[fm][fn][3]);
            *reinterpret_cast<__half2*>(smem + r0 * EP_PITCH + gcol * 2) = __floats2half2_rn(p00, p01);
            *reinterpret_cast<__half2*>(smem + r1 * EP_PITCH + gcol * 2) = __floats2half2_rn(p10, p11);
            s0 += p00 + p01;
            s1 += p10 + p11;
        }
        s0 += __shfl_xor_sync(0xffffffffu, s0, 1);
        s0 += __shfl_xor_sync(0xffffffffu, s0, 2);
        s1 += __shfl_xor_sync(0xffffffffu, s1, 1);
        s1 += __shfl_xor_sync(0xffffffffu, s1, 2);
        if ((lane & 3) == 0) {
            atomicAdd(&rowbuf[r0], s0);
            atomicAdd(&rowbuf[r1], s1);
        }
    }
    __syncthreads();

    // ------- cooperative coalesced store: 2048 x 16B chunks -------
    __half* eb = g_exp + ((size_t)bi * NROWS + (size_t)tn * BM) * MCOLS + (size_t)tm * BN;
    #pragma unroll
    for (int i = 0; i < 16; i++) {
        int c = tid + i * 128;             // 0..2047
        int row = c >> 4;                  // 16 chunks of 16B per 256B row
        int cc = c & 15;
        float4 v = *reinterpret_cast<float4*>(smem + row * EP_PITCH + cc * 16);
        *reinterpret_cast<float4*>(eb + (size_t)row * MCOLS + cc * 8) = v;
    }

    {
        size_t row = (size_t)bi * NROWS + (size_t)tn * BM + tid;
        g_partial[row * NTM + tm] = rowbuf[tid];
    }
}

// ------------- normalize: read fp16 exp, write fp32 out (forward order) ----
__global__ __launch_bounds__(256)
void norm_kernel(float* __restrict__ out) {
    const size_t r0 = (size_t)blockIdx.x * 2;
    float sa = 0.f, sb = 0.f;
    #pragma unroll
    for (int i = 0; i < NTM; i++) {
        sa += g_partial[r0 * NTM + i];
        sb += g_partial[(r0 + 1) * NTM + i];
    }
    const float ra = 1.0f / sa, rb = 1.0f / sb;

    const __half2* ea  = (const __half2*)(g_exp + r0 * MCOLS);
    const __half2* ebp = (const __half2*)(g_exp + (r0 + 1) * MCOLS);
    float4* oa = (float4*)(out + r0 * MCOLS);
    float4* ob = (float4*)(out + (r0 + 1) * MCOLS);
    const int t = threadIdx.x;

    #pragma unroll
    for (int j = 0; j < 2; j++) {
        int i = t + j * 256;                 // 0..511 float4 per row
        float2 f0 = __half22float2(ea[2 * i]);
        float2 f1 = __half22float2(ea[2 * i + 1]);
        float4 v; v.x = f0.x * ra; v.y = f0.y * ra; v.z = f1.x * ra; v.w = f1.y * ra;
        oa[i] = v;
        f0 = __half22float2(ebp[2 * i]);
        f1 = __half22float2(ebp[2 * i + 1]);
        v.x = f0.x * rb; v.y = f0.y * rb; v.z = f1.x * rb; v.w = f1.y * rb;
        ob[i] = v;
    }
}

// ------------- launch --------------------------------------------------------
extern "C" void kernel_launch(void* const* d_in, const int* in_sizes, int n_in,
                              void* d_out, int out_size) {
    const float4* q = (const float4*)d_in[0];
    const float4* k = (const float4*)d_in[1];
    float* out = (float*)d_out;

    cudaFuncSetAttribute(scores_kernel,
                         cudaFuncAttributeMaxDynamicSharedMemorySize, SMEM_BYTES);

    convert_kernel<<<16384, 256>>>(q, k);
    dim3 grid(NTM, NROWS / BM, BATCH);   // 16 x 16 x 16
    scores_kernel<<<grid, 128, SMEM_BYTES>>>();
    norm_kernel<<<BATCH * NROWS / 2, 256>>>(out);
}